// round 2
// baseline (speedup 1.0000x reference)
#include <cuda_runtime.h>
#include <cstdint>

#define T_STEPS 512
#define HDIM 20
#define BPB 32          // batch elements per block (8 per warp, 4 lanes each)
#define NTHREADS 128

typedef unsigned long long u64;

// packed f32x2 FMA: acc = a*b + acc  (two fp32 FMAs per lane per instr)
__device__ __forceinline__ void ffma2(u64& acc, u64 a, u64 b) {
    asm("fma.rn.f32x2 %0, %1, %2, %0;" : "+l"(acc) : "l"(a), "l"(b));
}
__device__ __forceinline__ u64 pack2(float lo, float hi) {
    u64 r; asm("mov.b64 %0, {%1, %2};" : "=l"(r) : "f"(lo), "f"(hi)); return r;
}
__device__ __forceinline__ float2 unpack2(u64 v) {
    float2 r; asm("mov.b64 {%0, %1}, %2;" : "=f"(r.x), "=f"(r.y) : "l"(v)); return r;
}

// accurate-enough tanh: (e^{2|x|}-1)/(e^{2|x|}+1) with sign restore.
// ex2.approx + rcp.approx => abs error ~2-3e-7 everywhere (incl. small x).
__device__ __forceinline__ float tanh_fast(float x) {
    float ax = fminf(fabsf(x), 15.0f);
    float e;
    asm("ex2.approx.f32 %0, %1;" : "=f"(e) : "f"(ax * 2.8853900817779268f)); // 2*log2(e)
    float rr;
    asm("rcp.approx.f32 %0, %1;" : "=f"(rr) : "f"(e + 1.0f));
    float t = (e - 1.0f) * rr;
    return copysignf(t, x);
}

__global__ __launch_bounds__(NTHREADS)
void rnn3_kernel(
    const float* __restrict__ x,
    const float* __restrict__ w_ih0, const float* __restrict__ w_hh0,
    const float* __restrict__ b_ih0, const float* __restrict__ b_hh0,
    const float* __restrict__ w_ih1, const float* __restrict__ w_hh1,
    const float* __restrict__ b_ih1, const float* __restrict__ b_hh1,
    const float* __restrict__ w_ih2, const float* __restrict__ w_hh2,
    const float* __restrict__ b_ih2, const float* __restrict__ b_hh2,
    const float* __restrict__ fc_w, const float* __restrict__ fc_b,
    float* __restrict__ out)
{
    // weights: [0]=w_hh0, [1]=w_ih1, [2]=w_hh1, [3]=w_ih2, [4]=w_hh2  (row-major [j][k])
    __shared__ __align__(16) float w_s[5][HDIM * HDIM];
    // hidden state ping-pong: [buf][batch_in_block][layer*20 + j]
    __shared__ __align__(16) float hbuf[2][BPB][3 * HDIM];

    const int tid = threadIdx.x;

    for (int i = tid; i < HDIM * HDIM; i += NTHREADS) {
        w_s[0][i] = w_hh0[i];
        w_s[1][i] = w_ih1[i];
        w_s[2][i] = w_hh1[i];
        w_s[3][i] = w_ih2[i];
        w_s[4][i] = w_hh2[i];
    }
    for (int i = tid; i < 2 * BPB * 3 * HDIM; i += NTHREADS)
        (&hbuf[0][0][0])[i] = 0.0f;
    __syncthreads();

    const int lane = tid & 31;
    const int warp = tid >> 5;
    const int gi   = lane >> 2;          // group (batch) index within warp
    const int sub  = lane & 3;           // lane within 4-lane group
    const int bib  = warp * 8 + gi;      // batch index within block
    const int b    = blockIdx.x * BPB + bib;
    const int j0   = sub * 5;            // this lane owns h[j0 .. j0+4]

    // per-lane constants in registers
    float bias0[5], bias1[5], bias2[5], wih0r[5];
#pragma unroll
    for (int jj = 0; jj < 5; jj++) {
        int j = j0 + jj;
        bias0[jj] = b_ih0[j] + b_hh0[j];
        bias1[jj] = b_ih1[j] + b_hh1[j];
        bias2[jj] = b_ih2[j] + b_hh2[j];
        wih0r[jj] = w_ih0[j];            // (H, IN=1)
    }

    const float* xrow = x + (size_t)b * T_STEPS;

    int rb = 0;
#pragma unroll 1
    for (int t = 0; t < T_STEPS; t++) {
        const int wb = rb ^ 1;
        const float xv = __ldg(&xrow[t]);

        // ---------------- Layer 0: h0_new = tanh(x*wih0 + bias0 + whh0 @ h0) --------
        {
            const ulonglong2* h0 = (const ulonglong2*)&hbuf[rb][bib][0];
            u64 hp[10];
#pragma unroll
            for (int q = 0; q < 5; q++) { ulonglong2 v = h0[q]; hp[2*q] = v.x; hp[2*q+1] = v.y; }
            float hn[5];
#pragma unroll
            for (int jj = 0; jj < 5; jj++) {
                const ulonglong2* wr = (const ulonglong2*)&w_s[0][(j0 + jj) * HDIM];
                u64 acc = pack2(fmaf(xv, wih0r[jj], bias0[jj]), 0.0f);
#pragma unroll
                for (int q = 0; q < 5; q++) {
                    ulonglong2 wv = wr[q];
                    ffma2(acc, hp[2*q],     wv.x);
                    ffma2(acc, hp[2*q + 1], wv.y);
                }
                float2 p = unpack2(acc);
                hn[jj] = tanh_fast(p.x + p.y);
            }
#pragma unroll
            for (int jj = 0; jj < 5; jj++) hbuf[wb][bib][j0 + jj] = hn[jj];
        }
        __syncwarp();

        // ---------------- Layer 1: h1_new = tanh(wih1 @ h0_new + bias1 + whh1 @ h1) -
        {
            const ulonglong2* hA = (const ulonglong2*)&hbuf[wb][bib][0];      // h0 new
            const ulonglong2* hB = (const ulonglong2*)&hbuf[rb][bib][HDIM];   // h1 old
            u64 ha[10], hb2[10];
#pragma unroll
            for (int q = 0; q < 5; q++) {
                ulonglong2 va = hA[q]; ha[2*q] = va.x; ha[2*q+1] = va.y;
                ulonglong2 vb = hB[q]; hb2[2*q] = vb.x; hb2[2*q+1] = vb.y;
            }
            float hn[5];
#pragma unroll
            for (int jj = 0; jj < 5; jj++) {
                const ulonglong2* wi = (const ulonglong2*)&w_s[1][(j0 + jj) * HDIM];
                const ulonglong2* wh = (const ulonglong2*)&w_s[2][(j0 + jj) * HDIM];
                u64 acc = pack2(bias1[jj], 0.0f);
#pragma unroll
                for (int q = 0; q < 5; q++) {
                    ulonglong2 wv = wi[q];
                    ffma2(acc, ha[2*q],     wv.x);
                    ffma2(acc, ha[2*q + 1], wv.y);
                }
#pragma unroll
                for (int q = 0; q < 5; q++) {
                    ulonglong2 wv = wh[q];
                    ffma2(acc, hb2[2*q],     wv.x);
                    ffma2(acc, hb2[2*q + 1], wv.y);
                }
                float2 p = unpack2(acc);
                hn[jj] = tanh_fast(p.x + p.y);
            }
#pragma unroll
            for (int jj = 0; jj < 5; jj++) hbuf[wb][bib][HDIM + j0 + jj] = hn[jj];
        }
        __syncwarp();

        // ---------------- Layer 2: h2_new = tanh(wih2 @ h1_new + bias2 + whh2 @ h2) -
        {
            const ulonglong2* hA = (const ulonglong2*)&hbuf[wb][bib][HDIM];     // h1 new
            const ulonglong2* hB = (const ulonglong2*)&hbuf[rb][bib][2 * HDIM]; // h2 old
            u64 ha[10], hb2[10];
#pragma unroll
            for (int q = 0; q < 5; q++) {
                ulonglong2 va = hA[q]; ha[2*q] = va.x; ha[2*q+1] = va.y;
                ulonglong2 vb = hB[q]; hb2[2*q] = vb.x; hb2[2*q+1] = vb.y;
            }
            float hn[5];
#pragma unroll
            for (int jj = 0; jj < 5; jj++) {
                const ulonglong2* wi = (const ulonglong2*)&w_s[3][(j0 + jj) * HDIM];
                const ulonglong2* wh = (const ulonglong2*)&w_s[4][(j0 + jj) * HDIM];
                u64 acc = pack2(bias2[jj], 0.0f);
#pragma unroll
                for (int q = 0; q < 5; q++) {
                    ulonglong2 wv = wi[q];
                    ffma2(acc, ha[2*q],     wv.x);
                    ffma2(acc, ha[2*q + 1], wv.y);
                }
#pragma unroll
                for (int q = 0; q < 5; q++) {
                    ulonglong2 wv = wh[q];
                    ffma2(acc, hb2[2*q],     wv.x);
                    ffma2(acc, hb2[2*q + 1], wv.y);
                }
                float2 p = unpack2(acc);
                hn[jj] = tanh_fast(p.x + p.y);
            }
#pragma unroll
            for (int jj = 0; jj < 5; jj++) hbuf[wb][bib][2 * HDIM + j0 + jj] = hn[jj];
        }
        __syncwarp();

        rb = wb;
    }

    // ---------------- FC epilogue: out[b] = h2_last . fc_w + fc_b ----------------
    float s = 0.0f;
#pragma unroll
    for (int jj = 0; jj < 5; jj++)
        s += hbuf[rb][bib][2 * HDIM + j0 + jj] * __ldg(&fc_w[j0 + jj]);
    s += __shfl_xor_sync(0xffffffffu, s, 1);
    s += __shfl_xor_sync(0xffffffffu, s, 2);
    if (sub == 0) out[b] = s + __ldg(&fc_b[0]);
}

extern "C" void kernel_launch(void* const* d_in, const int* in_sizes, int n_in,
                              void* d_out, int out_size) {
    (void)in_sizes; (void)n_in; (void)out_size;
    rnn3_kernel<<<256, NTHREADS>>>(
        (const float*)d_in[0],
        (const float*)d_in[1],  (const float*)d_in[2],
        (const float*)d_in[3],  (const float*)d_in[4],
        (const float*)d_in[5],  (const float*)d_in[6],
        (const float*)d_in[7],  (const float*)d_in[8],
        (const float*)d_in[9],  (const float*)d_in[10],
        (const float*)d_in[11], (const float*)d_in[12],
        (const float*)d_in[13], (const float*)d_in[14],
        (float*)d_out);
}

// round 3
// speedup vs baseline: 1.4095x; 1.4095x over previous
#include <cuda_runtime.h>
#include <cstdint>

#define T_STEPS 512
#define HDIM 20
#define BPB 32          // batches per block: 16 groups x 2 batches
#define NTHREADS 64     // 2 warps; warp = 8 groups of 4 lanes

typedef unsigned long long u64;

__device__ __forceinline__ void ffma2(u64& acc, u64 a, u64 b) {
    asm("fma.rn.f32x2 %0, %1, %2, %0;" : "+l"(acc) : "l"(a), "l"(b));
}
__device__ __forceinline__ u64 pack2(float lo, float hi) {
    u64 r; asm("mov.b64 %0, {%1, %2};" : "=l"(r) : "f"(lo), "f"(hi)); return r;
}
__device__ __forceinline__ float2 unpack2(u64 v) {
    float2 r; asm("mov.b64 {%0, %1}, %2;" : "=f"(r.x), "=f"(r.y) : "l"(v)); return r;
}

// tanh via ex2.approx + rcp.approx: abs err ~2-3e-7.
__device__ __forceinline__ float tanh_fast(float x) {
    float ax = fminf(fabsf(x), 15.0f);
    float e;
    asm("ex2.approx.f32 %0, %1;" : "=f"(e) : "f"(ax * 2.8853900817779268f));
    float rr;
    asm("rcp.approx.f32 %0, %1;" : "=f"(rr) : "f"(e + 1.0f));
    float t = (e - 1.0f) * rr;
    return copysignf(t, x);
}

__global__ __launch_bounds__(NTHREADS)
void rnn3_kernel(
    const float* __restrict__ x,
    const float* __restrict__ w_ih0, const float* __restrict__ w_hh0,
    const float* __restrict__ b_ih0, const float* __restrict__ b_hh0,
    const float* __restrict__ w_ih1, const float* __restrict__ w_hh1,
    const float* __restrict__ b_ih1, const float* __restrict__ b_hh1,
    const float* __restrict__ w_ih2, const float* __restrict__ w_hh2,
    const float* __restrict__ b_ih2, const float* __restrict__ b_hh2,
    const float* __restrict__ fc_w, const float* __restrict__ fc_b,
    float* __restrict__ out)
{
    // [0]=w_hh0, [1]=w_ih1, [2]=w_hh1, [3]=w_ih2, [4]=w_hh2  row-major [j][k]
    __shared__ __align__(16) float w_s[5][HDIM * HDIM];
    // hidden ping-pong: [buf][batch_in_block][layer*20 + j]; 60-float stride = 240B
    // (odd multiple of 16B -> 8 groups hit distinct 16B phases: conflict-free)
    __shared__ __align__(16) float hbuf[2][BPB][3 * HDIM];

    const int tid = threadIdx.x;

    for (int i = tid; i < HDIM * HDIM; i += NTHREADS) {
        w_s[0][i] = w_hh0[i];
        w_s[1][i] = w_ih1[i];
        w_s[2][i] = w_hh1[i];
        w_s[3][i] = w_ih2[i];
        w_s[4][i] = w_hh2[i];
    }
    for (int i = tid; i < 2 * BPB * 3 * HDIM; i += NTHREADS)
        (&hbuf[0][0][0])[i] = 0.0f;
    __syncthreads();

    const int lane = tid & 31;
    const int warp = tid >> 5;
    const int gi   = lane >> 2;
    const int sub  = lane & 3;
    const int bib0 = warp * 8 + gi;        // batch slot 0 (SoA across slots)
    const int bib1 = 16 + warp * 8 + gi;   // batch slot 1
    const int b0   = blockIdx.x * BPB + bib0;
    const int b1   = blockIdx.x * BPB + bib1;
    const int j0   = sub * 5;              // this lane owns rows j0..j0+4

    float bias0[5], bias1[5], bias2[5], wih0r[5];
#pragma unroll
    for (int jj = 0; jj < 5; jj++) {
        int j = j0 + jj;
        bias0[jj] = b_ih0[j] + b_hh0[j];
        bias1[jj] = b_ih1[j] + b_hh1[j];
        bias2[jj] = b_ih2[j] + b_hh2[j];
        wih0r[jj] = w_ih0[j];
    }

    const float* xrow0 = x + (size_t)b0 * T_STEPS;
    const float* xrow1 = x + (size_t)b1 * T_STEPS;

    int rb = 0;
#pragma unroll 1
    for (int t = 0; t < T_STEPS; t++) {
        const int wb = rb ^ 1;
        const float xv0 = __ldg(&xrow0[t]);
        const float xv1 = __ldg(&xrow1[t]);

        // ========== Layer 0: h0' = tanh(x*wih0 + bias0 + whh0 @ h0) ==========
        {
            u64 a0[5], a1[5];
#pragma unroll
            for (int jj = 0; jj < 5; jj++) {
                a0[jj] = pack2(fmaf(xv0, wih0r[jj], bias0[jj]), 0.0f);
                a1[jj] = pack2(fmaf(xv1, wih0r[jj], bias0[jj]), 0.0f);
            }
            const ulonglong2* h0a = (const ulonglong2*)&hbuf[rb][bib0][0];
            const ulonglong2* h0b = (const ulonglong2*)&hbuf[rb][bib1][0];
#pragma unroll
            for (int q = 0; q < 5; q++) {
                ulonglong2 hq0 = h0a[q];
                ulonglong2 hq1 = h0b[q];
#pragma unroll
                for (int jj = 0; jj < 5; jj++) {
                    ulonglong2 wq = ((const ulonglong2*)&w_s[0][(j0 + jj) * HDIM])[q];
                    ffma2(a0[jj], hq0.x, wq.x); ffma2(a0[jj], hq0.y, wq.y);
                    ffma2(a1[jj], hq1.x, wq.x); ffma2(a1[jj], hq1.y, wq.y);
                }
            }
#pragma unroll
            for (int jj = 0; jj < 5; jj++) {
                float2 p0 = unpack2(a0[jj]);
                float2 p1 = unpack2(a1[jj]);
                hbuf[wb][bib0][j0 + jj] = tanh_fast(p0.x + p0.y);
                hbuf[wb][bib1][j0 + jj] = tanh_fast(p1.x + p1.y);
            }
        }
        __syncwarp();

        // ========== Layer 1: h1' = tanh(wih1 @ h0' + bias1 + whh1 @ h1) ==========
        {
            u64 a0[5], a1[5];
#pragma unroll
            for (int jj = 0; jj < 5; jj++) {
                a0[jj] = pack2(bias1[jj], 0.0f);
                a1[jj] = pack2(bias1[jj], 0.0f);
            }
            const ulonglong2* hAa = (const ulonglong2*)&hbuf[wb][bib0][0];      // h0'
            const ulonglong2* hAb = (const ulonglong2*)&hbuf[wb][bib1][0];
            const ulonglong2* hBa = (const ulonglong2*)&hbuf[rb][bib0][HDIM];   // h1 old
            const ulonglong2* hBb = (const ulonglong2*)&hbuf[rb][bib1][HDIM];
#pragma unroll
            for (int q = 0; q < 5; q++) {
                ulonglong2 ha0 = hAa[q], ha1 = hAb[q];
                ulonglong2 hb0 = hBa[q], hb1 = hBb[q];
#pragma unroll
                for (int jj = 0; jj < 5; jj++) {
                    ulonglong2 wi = ((const ulonglong2*)&w_s[1][(j0 + jj) * HDIM])[q];
                    ulonglong2 wh = ((const ulonglong2*)&w_s[2][(j0 + jj) * HDIM])[q];
                    ffma2(a0[jj], ha0.x, wi.x); ffma2(a0[jj], ha0.y, wi.y);
                    ffma2(a0[jj], hb0.x, wh.x); ffma2(a0[jj], hb0.y, wh.y);
                    ffma2(a1[jj], ha1.x, wi.x); ffma2(a1[jj], ha1.y, wi.y);
                    ffma2(a1[jj], hb1.x, wh.x); ffma2(a1[jj], hb1.y, wh.y);
                }
            }
#pragma unroll
            for (int jj = 0; jj < 5; jj++) {
                float2 p0 = unpack2(a0[jj]);
                float2 p1 = unpack2(a1[jj]);
                hbuf[wb][bib0][HDIM + j0 + jj] = tanh_fast(p0.x + p0.y);
                hbuf[wb][bib1][HDIM + j0 + jj] = tanh_fast(p1.x + p1.y);
            }
        }
        __syncwarp();

        // ========== Layer 2: h2' = tanh(wih2 @ h1' + bias2 + whh2 @ h2) ==========
        {
            u64 a0[5], a1[5];
#pragma unroll
            for (int jj = 0; jj < 5; jj++) {
                a0[jj] = pack2(bias2[jj], 0.0f);
                a1[jj] = pack2(bias2[jj], 0.0f);
            }
            const ulonglong2* hAa = (const ulonglong2*)&hbuf[wb][bib0][HDIM];       // h1'
            const ulonglong2* hAb = (const ulonglong2*)&hbuf[wb][bib1][HDIM];
            const ulonglong2* hBa = (const ulonglong2*)&hbuf[rb][bib0][2 * HDIM];   // h2 old
            const ulonglong2* hBb = (const ulonglong2*)&hbuf[rb][bib1][2 * HDIM];
#pragma unroll
            for (int q = 0; q < 5; q++) {
                ulonglong2 ha0 = hAa[q], ha1 = hAb[q];
                ulonglong2 hb0 = hBa[q], hb1 = hBb[q];
#pragma unroll
                for (int jj = 0; jj < 5; jj++) {
                    ulonglong2 wi = ((const ulonglong2*)&w_s[3][(j0 + jj) * HDIM])[q];
                    ulonglong2 wh = ((const ulonglong2*)&w_s[4][(j0 + jj) * HDIM])[q];
                    ffma2(a0[jj], ha0.x, wi.x); ffma2(a0[jj], ha0.y, wi.y);
                    ffma2(a0[jj], hb0.x, wh.x); ffma2(a0[jj], hb0.y, wh.y);
                    ffma2(a1[jj], ha1.x, wi.x); ffma2(a1[jj], ha1.y, wi.y);
                    ffma2(a1[jj], hb1.x, wh.x); ffma2(a1[jj], hb1.y, wh.y);
                }
            }
#pragma unroll
            for (int jj = 0; jj < 5; jj++) {
                float2 p0 = unpack2(a0[jj]);
                float2 p1 = unpack2(a1[jj]);
                hbuf[wb][bib0][2 * HDIM + j0 + jj] = tanh_fast(p0.x + p0.y);
                hbuf[wb][bib1][2 * HDIM + j0 + jj] = tanh_fast(p1.x + p1.y);
            }
        }
        __syncwarp();

        rb = wb;
    }

    // ================= FC epilogue: out[b] = h2 . fc_w + fc_b =================
    float s0 = 0.0f, s1 = 0.0f;
#pragma unroll
    for (int jj = 0; jj < 5; jj++) {
        float w = __ldg(&fc_w[j0 + jj]);
        s0 += hbuf[rb][bib0][2 * HDIM + j0 + jj] * w;
        s1 += hbuf[rb][bib1][2 * HDIM + j0 + jj] * w;
    }
    s0 += __shfl_xor_sync(0xffffffffu, s0, 1);
    s0 += __shfl_xor_sync(0xffffffffu, s0, 2);
    s1 += __shfl_xor_sync(0xffffffffu, s1, 1);
    s1 += __shfl_xor_sync(0xffffffffu, s1, 2);
    if (sub == 0) {
        float fb = __ldg(&fc_b[0]);
        out[b0] = s0 + fb;
        out[b1] = s1 + fb;
    }
}

extern "C" void kernel_launch(void* const* d_in, const int* in_sizes, int n_in,
                              void* d_out, int out_size) {
    (void)in_sizes; (void)n_in; (void)out_size;
    rnn3_kernel<<<256, NTHREADS>>>(
        (const float*)d_in[0],
        (const float*)d_in[1],  (const float*)d_in[2],
        (const float*)d_in[3],  (const float*)d_in[4],
        (const float*)d_in[5],  (const float*)d_in[6],
        (const float*)d_in[7],  (const float*)d_in[8],
        (const float*)d_in[9],  (const float*)d_in[10],
        (const float*)d_in[11], (const float*)d_in[12],
        (const float*)d_in[13], (const float*)d_in[14],
        (float*)d_out);
}